// round 13
// baseline (speedup 1.0000x reference)
#include <cuda_runtime.h>
#include <cuda_fp16.h>
#include <cstdint>
#include <cstddef>

#define D_MODEL 1024
#define N_HEADS 16
#define D_HEAD 64
#define BATCH 2
#define SEQ 2048
#define M_ROWS (BATCH * SEQ)   // 4096

// Scratch (allocation-free rule: device globals)
__device__ __half g_qkv[(size_t)M_ROWS * 3 * D_MODEL];     // [4096,3072] fp16
__device__ __half g_ctx[(size_t)M_ROWS * D_MODEL];         // [4096,1024] fp16
__device__ __half g_xh[(size_t)M_ROWS * D_MODEL];          // fp16(x)
__device__ __half g_wqkvh[(size_t)D_MODEL * 3 * D_MODEL];  // fp16(w_qkv) [K,N]
__device__ __half g_wprojh[(size_t)D_MODEL * D_MODEL];     // fp16(w_proj) [K,N]

// ---------------------------------------------------------------------------
// helpers
// ---------------------------------------------------------------------------
__device__ __forceinline__ float ex2(float x) {
    float r;
    asm("ex2.approx.ftz.f32 %0, %1;" : "=f"(r) : "f"(x));
    return r;
}
__device__ __forceinline__ void cpa16(uint32_t dst, const void* src) {
    asm volatile("cp.async.cg.shared.global [%0], [%1], 16;\n" :: "r"(dst), "l"(src));
}
__device__ __forceinline__ uint32_t sm_u32(const void* p) {
    return (uint32_t)__cvta_generic_to_shared(p);
}
__device__ __forceinline__ void ldsm4(uint32_t& r0, uint32_t& r1, uint32_t& r2, uint32_t& r3,
                                      uint32_t addr) {
    asm volatile("ldmatrix.sync.aligned.m8n8.x4.shared.b16 {%0,%1,%2,%3}, [%4];"
                 : "=r"(r0), "=r"(r1), "=r"(r2), "=r"(r3) : "r"(addr));
}
__device__ __forceinline__ void ldsm4t(uint32_t& r0, uint32_t& r1, uint32_t& r2, uint32_t& r3,
                                       uint32_t addr) {
    asm volatile("ldmatrix.sync.aligned.m8n8.x4.trans.shared.b16 {%0,%1,%2,%3}, [%4];"
                 : "=r"(r0), "=r"(r1), "=r"(r2), "=r"(r3) : "r"(addr));
}
// D += A @ B  (m16n8k16, fp16 in, fp32 accumulate)
__device__ __forceinline__ void mma16(float4& d, const uint32_t* a, const uint32_t* b) {
    asm volatile(
        "mma.sync.aligned.m16n8k16.row.col.f32.f16.f16.f32 "
        "{%0,%1,%2,%3},{%4,%5,%6,%7},{%8,%9},{%0,%1,%2,%3};"
        : "+f"(d.x), "+f"(d.y), "+f"(d.z), "+f"(d.w)
        : "r"(a[0]), "r"(a[1]), "r"(a[2]), "r"(a[3]),
          "r"(b[0]), "r"(b[1]));
}
__device__ __forceinline__ uint32_t pack_h2(float a, float b) {
    __half2 h = __floats2half2_rn(a, b);
    return *(uint32_t*)&h;
}

// ---------------------------------------------------------------------------
// prep: fp32 -> fp16 for x, w_qkv, w_proj in ONE launch (float4 granularity)
// ---------------------------------------------------------------------------
#define N4_X  (M_ROWS * D_MODEL / 4)            // 1048576
#define N4_WQ (D_MODEL * 3 * D_MODEL / 4)       // 786432
#define N4_WP (D_MODEL * D_MODEL / 4)           // 262144

__global__ void f2h3(const float4* __restrict__ x, const float4* __restrict__ wq,
                     const float4* __restrict__ wp,
                     __half2* __restrict__ xo, __half2* __restrict__ wqo,
                     __half2* __restrict__ wpo)
{
    const int i = blockIdx.x * blockDim.x + threadIdx.x;
    const float4* in;
    __half2* out;
    int j;
    if (i < N4_X)                { in = x;  out = xo;  j = i; }
    else if (i < N4_X + N4_WQ)   { in = wq; out = wqo; j = i - N4_X; }
    else                         { in = wp; out = wpo; j = i - N4_X - N4_WQ; }
    float4 v = in[j];
    out[j * 2]     = __floats2half2_rn(v.x, v.y);
    out[j * 2 + 1] = __floats2half2_rn(v.z, v.w);
}

// ---------------------------------------------------------------------------
// GEMM: C[M,N] = A[M,1024] @ B[1024,N], fp16 in, fp32 accum, fp16/fp32 out.
// 128x128x32 block tile, 8 warps (2x4), warp tile 64x32, 4-stage cp.async.
// (R9 config — best measured: 48.9% tensor. FROZEN.)
// ---------------------------------------------------------------------------
#define GSTAGES 4
#define A_STB (128 * 80)    // 10240 B / stage
#define B_STB (32 * 256)    // 8192 B / stage
#define GEMM_SMEM (GSTAGES * (A_STB + B_STB))   // 73728 B

template<bool HALF_OUT>
__global__ __launch_bounds__(256, 2)
void gemm_h(const __half* __restrict__ A, const __half* __restrict__ B,
            void* __restrict__ Cv, int N, int qcols, float qscale)
{
    extern __shared__ char smc[];
    const uint32_t Ab = sm_u32(smc);
    const uint32_t Bb = Ab + GSTAGES * A_STB;

    const int tid  = threadIdx.x;
    const int lane = tid & 31;
    const int warp = tid >> 5;
    const int g    = lane >> 2;
    const int c    = lane & 3;
    const int l15  = lane & 15;
    const int l16  = lane >> 4;
    const int wm   = (warp & 1) * 64;
    const int wn   = (warp >> 1) * 32;
    const int m0   = blockIdx.y * 128;
    const int n0   = blockIdx.x * 128;

    auto stage = [&](int ch) {
        const int s  = ch & 3;
        const int k0 = ch * 32;
#pragma unroll
        for (int i = 0; i < 2; ++i) {              // A: 128 rows x 4 chunks
            const int id = tid + 256 * i;
            const int row = id >> 2, cc = id & 3;
            cpa16(Ab + s * A_STB + row * 80 + cc * 16,
                  A + (size_t)(m0 + row) * 1024 + k0 + cc * 8);
        }
#pragma unroll
        for (int i = 0; i < 2; ++i) {              // B: 32 k x 16 chunks
            const int id = tid + 256 * i;
            const int row = id >> 4, cc = id & 15;
            cpa16(Bb + s * B_STB + row * 256 + ((cc ^ (row & 7)) * 16),
                  B + (size_t)(k0 + row) * N + n0 + cc * 8);
        }
    };

    stage(0); asm volatile("cp.async.commit_group;\n");
    stage(1); asm volatile("cp.async.commit_group;\n");
    stage(2); asm volatile("cp.async.commit_group;\n");

    float4 acc[4][4];
#pragma unroll
    for (int i = 0; i < 4; ++i)
#pragma unroll
        for (int j = 0; j < 4; ++j) acc[i][j] = make_float4(0.f, 0.f, 0.f, 0.f);

    for (int ch = 0; ch < 32; ++ch) {
        asm volatile("cp.async.wait_group %0;\n" :: "n"(2));
        __syncthreads();

        if (ch + 3 < 32) stage(ch + 3);
        asm volatile("cp.async.commit_group;\n");

        const uint32_t As = Ab + (ch & 3) * A_STB;
        const uint32_t Bs = Bb + (ch & 3) * B_STB;

#pragma unroll
        for (int kc = 0; kc < 2; ++kc) {
            uint32_t af[4][4];
#pragma unroll
            for (int i = 0; i < 4; ++i)
                ldsm4(af[i][0], af[i][1], af[i][2], af[i][3],
                      As + (wm + i * 16 + l15) * 80 + (kc * 2 + l16) * 16);
            uint32_t bf[4][2];
#pragma unroll
            for (int j2 = 0; j2 < 2; ++j2) {
                const int krow = kc * 16 + l15;
                const int cn   = (wn >> 3) + j2 * 2 + l16;
                ldsm4t(bf[j2 * 2][0], bf[j2 * 2][1], bf[j2 * 2 + 1][0], bf[j2 * 2 + 1][1],
                       Bs + krow * 256 + ((cn ^ (krow & 7)) * 16));
            }
#pragma unroll
            for (int i = 0; i < 4; ++i)
#pragma unroll
                for (int j = 0; j < 4; ++j)
                    mma16(acc[i][j], af[i], bf[j]);
        }
    }

    // epilogue (q-column scaling is uniform per CTA: 1024 % 128 == 0)
    const float sc = (n0 < qcols) ? qscale : 1.0f;
#pragma unroll
    for (int i = 0; i < 4; ++i) {
        const int r = m0 + wm + i * 16 + g;
#pragma unroll
        for (int j = 0; j < 4; ++j) {
            const int cl = n0 + wn + j * 8 + 2 * c;
            if (HALF_OUT) {
                __half* C = (__half*)Cv;
                *(__half2*)&C[(size_t)r * N + cl] =
                    __floats2half2_rn(acc[i][j].x * sc, acc[i][j].y * sc);
                *(__half2*)&C[(size_t)(r + 8) * N + cl] =
                    __floats2half2_rn(acc[i][j].z * sc, acc[i][j].w * sc);
            } else {
                float* C = (float*)Cv;
                *(float2*)&C[(size_t)r * N + cl] = make_float2(acc[i][j].x, acc[i][j].y);
                *(float2*)&C[(size_t)(r + 8) * N + cl] = make_float2(acc[i][j].z, acc[i][j].w);
            }
        }
    }
}

// ---------------------------------------------------------------------------
// Flash attention, causal, fp16 mma + ldmatrix.
// Br=128 with FOUR warps of 32 q-rows each (two 16-row groups per warp):
// every K/V ldmatrix now feeds TWO row-groups, halving the duplicated K/V
// smem reads per CTA (the measured fa bottleneck). 2 CTAs/SM keeps 8
// warps/SM. 128-key super-tile staging (one barrier per 128 keys), P in
// registers, deferred per-thread l, conditional rescale. Math bit-identical
// to R9/R12 per row.
// ---------------------------------------------------------------------------
#define KV128_B (128 * 144)                    // 18432 B per K / V 128-row tile
#define FA_SMEM (4 * KV128_B)                  // 73728 B (2 K + 2 V)

__global__ __launch_bounds__(128, 2)
void fa_h(const __half* __restrict__ qkv, __half* __restrict__ ctx)
{
    extern __shared__ char fsc[];
    const uint32_t Kb0 = sm_u32(fsc);              // K buf 0, K buf 1
    const uint32_t Vb0 = Kb0 + 2 * KV128_B;        // V buf 0, V buf 1

    const int tid  = threadIdx.x;
    const int lane = tid & 31;
    const int warp = tid >> 5;                     // 0..3
    const int g    = lane >> 2;
    const int c    = lane & 3;
    const int l15  = lane & 15;
    const int l16  = lane >> 4;
    const int bh   = blockIdx.y;
    const int b    = bh >> 4;
    const int h    = bh & 15;
    const int q0   = (gridDim.x - 1 - blockIdx.x) * 128;   // big blocks first
    const int wrow = warp * 32;                    // 32 q-rows per warp

    const __half* qbase = qkv + (size_t)(b * SEQ) * 3072 + h * 64;

    // staging: 128 rows x 8 chunks x 2 arrays = 2048 slots over 128 threads
    const int srow = tid >> 3;            // 0..15
    const int scc  = tid & 7;
    auto stage_kv = [&](int J, int s) {   // stage keys [J, J+128)
        const uint32_t kd = Kb0 + s * KV128_B;
        const uint32_t vd = Vb0 + s * KV128_B;
#pragma unroll
        for (int i = 0; i < 8; ++i) {
            const int row = srow + 16 * i;
            const __half* kg = qbase + (size_t)(J + row) * 3072 + 1024 + scc * 8;
            cpa16(kd + row * 144 + scc * 16, kg);
            cpa16(vd + row * 144 + scc * 16, kg + 1024);
        }
    };

    // Q fragments for both 16-row groups (pre-scaled in QKV GEMM epilogue)
    uint32_t qf[2][4][4];
#pragma unroll
    for (int rg = 0; rg < 2; ++rg) {
        const __half* r0 = qbase + (size_t)(q0 + wrow + rg * 16 + g) * 3072;
        const __half* r1 = r0 + 8 * 3072;
#pragma unroll
        for (int kc = 0; kc < 4; ++kc) {
            qf[rg][kc][0] = *(const uint32_t*)(r0 + kc * 16 + 2 * c);
            qf[rg][kc][1] = *(const uint32_t*)(r1 + kc * 16 + 2 * c);
            qf[rg][kc][2] = *(const uint32_t*)(r0 + kc * 16 + 8 + 2 * c);
            qf[rg][kc][3] = *(const uint32_t*)(r1 + kc * 16 + 8 + 2 * c);
        }
    }

    float4 oacc[2][8];
#pragma unroll
    for (int rg = 0; rg < 2; ++rg)
#pragma unroll
        for (int i = 0; i < 8; ++i) oacc[rg][i] = make_float4(0.f, 0.f, 0.f, 0.f);
    float m0v[2] = { -1e30f, -1e30f };   // per row-group: rows (g), rows (g+8)
    float m1v[2] = { -1e30f, -1e30f };
    float lp0[2] = { 0.f, 0.f };
    float lp1[2] = { 0.f, 0.f };

    // prologue: stage super-tile 0 into buffer 0
    stage_kv(0, 0);
    asm volatile("cp.async.commit_group;\n");

    int s = 0;
    for (int J = 0; J <= q0; J += 128, s ^= 1) {
        asm volatile("cp.async.wait_group 0;\n");   // super-tile J ready
        __syncthreads();   // publishes J AND proves buffer s^1 is free

        if (J + 128 <= q0) {
            stage_kv(J + 128, s ^ 1);
            asm volatile("cp.async.commit_group;\n");
        }

#pragma unroll
        for (int half = 0; half < 2; ++half) {
            const int j0 = J + half * 64;
            if (j0 > q0 + wrow + 31) break;   // all 32 rows masked

            const uint32_t Kb = Kb0 + s * KV128_B + half * (64 * 144);
            const uint32_t Vb = Vb0 + s * KV128_B + half * (64 * 144);

            // ---- S = Q @ K^T: each K ldsm feeds both row groups ----
            float4 sacc[2][8];
#pragma unroll
            for (int rg = 0; rg < 2; ++rg)
#pragma unroll
                for (int i = 0; i < 8; ++i) sacc[rg][i] = make_float4(0.f, 0.f, 0.f, 0.f);
#pragma unroll
            for (int kc = 0; kc < 4; ++kc) {
#pragma unroll
                for (int grp = 0; grp < 4; ++grp) {
                    uint32_t r0, r1, r2, r3;
                    ldsm4(r0, r1, r2, r3,
                          Kb + (grp * 16 + l15) * 144 + (kc * 2 + l16) * 16);
                    uint32_t b0[2] = { r0, r2 };
                    uint32_t b1[2] = { r1, r3 };
#pragma unroll
                    for (int rg = 0; rg < 2; ++rg) {
                        mma16(sacc[rg][2 * grp],     qf[rg][kc], b0);
                        mma16(sacc[rg][2 * grp + 1], qf[rg][kc], b1);
                    }
                }
            }

            // ---- causal mask (only near the diagonal) ----
            if (j0 + 63 > q0 + wrow) {
#pragma unroll
                for (int rg = 0; rg < 2; ++rg) {
                    const int rgb = q0 + wrow + rg * 16 + g;
#pragma unroll
                    for (int nt = 0; nt < 8; ++nt) {
                        const int cl = j0 + nt * 8 + 2 * c;
                        if (cl     > rgb)     sacc[rg][nt].x = -1e30f;
                        if (cl + 1 > rgb)     sacc[rg][nt].y = -1e30f;
                        if (cl     > rgb + 8) sacc[rg][nt].z = -1e30f;
                        if (cl + 1 > rgb + 8) sacc[rg][nt].w = -1e30f;
                    }
                }
            }

            // ---- online softmax + pack (per row group) ----
            uint32_t pf[2][16];
#pragma unroll
            for (int rg = 0; rg < 2; ++rg) {
                float tm0 = -1e30f, tm1 = -1e30f;
#pragma unroll
                for (int nt = 0; nt < 8; ++nt) {
                    tm0 = fmaxf(tm0, fmaxf(sacc[rg][nt].x, sacc[rg][nt].y));
                    tm1 = fmaxf(tm1, fmaxf(sacc[rg][nt].z, sacc[rg][nt].w));
                }
                tm0 = fmaxf(tm0, __shfl_xor_sync(0xffffffffu, tm0, 1));
                tm0 = fmaxf(tm0, __shfl_xor_sync(0xffffffffu, tm0, 2));
                tm1 = fmaxf(tm1, __shfl_xor_sync(0xffffffffu, tm1, 1));
                tm1 = fmaxf(tm1, __shfl_xor_sync(0xffffffffu, tm1, 2));

                if (tm0 > m0v[rg] || tm1 > m1v[rg]) {   // max moved: rescale
                    const float nm0 = fmaxf(m0v[rg], tm0);
                    const float nm1 = fmaxf(m1v[rg], tm1);
                    const float cr0 = ex2(m0v[rg] - nm0);
                    const float cr1 = ex2(m1v[rg] - nm1);
                    m0v[rg] = nm0; m1v[rg] = nm1;
                    lp0[rg] *= cr0; lp1[rg] *= cr1;
#pragma unroll
                    for (int nt = 0; nt < 8; ++nt) {
                        oacc[rg][nt].x *= cr0; oacc[rg][nt].y *= cr0;
                        oacc[rg][nt].z *= cr1; oacc[rg][nt].w *= cr1;
                    }
                }

                float ps0 = 0.f, ps1 = 0.f;
#pragma unroll
                for (int nt = 0; nt < 8; ++nt) {
                    sacc[rg][nt].x = ex2(sacc[rg][nt].x - m0v[rg]);
                    sacc[rg][nt].y = ex2(sacc[rg][nt].y - m0v[rg]);
                    sacc[rg][nt].z = ex2(sacc[rg][nt].z - m1v[rg]);
                    sacc[rg][nt].w = ex2(sacc[rg][nt].w - m1v[rg]);
                    ps0 += sacc[rg][nt].x + sacc[rg][nt].y;
                    ps1 += sacc[rg][nt].z + sacc[rg][nt].w;
                }
                lp0[rg] += ps0;
                lp1[rg] += ps1;

#pragma unroll
                for (int nt = 0; nt < 8; ++nt) {
                    pf[rg][nt * 2]     = pack_h2(sacc[rg][nt].x, sacc[rg][nt].y);
                    pf[rg][nt * 2 + 1] = pack_h2(sacc[rg][nt].z, sacc[rg][nt].w);
                }
            }

            // ---- O += P @ V: each V ldsm feeds both row groups ----
#pragma unroll
            for (int kc = 0; kc < 4; ++kc) {
#pragma unroll
                for (int j2 = 0; j2 < 4; ++j2) {
                    uint32_t r0, r1, r2, r3;
                    ldsm4t(r0, r1, r2, r3,
                           Vb + (kc * 16 + l15) * 144 + (j2 * 2 + l16) * 16);
                    uint32_t b0[2] = { r0, r1 };
                    uint32_t b1[2] = { r2, r3 };
#pragma unroll
                    for (int rg = 0; rg < 2; ++rg) {
                        mma16(oacc[rg][2 * j2],     &pf[rg][kc * 4], b0);
                        mma16(oacc[rg][2 * j2 + 1], &pf[rg][kc * 4], b1);
                    }
                }
            }
        }
    }

    // ---- final l reduction + normalize + write ctx (fp16) ----
#pragma unroll
    for (int rg = 0; rg < 2; ++rg) {
        lp0[rg] += __shfl_xor_sync(0xffffffffu, lp0[rg], 1);
        lp0[rg] += __shfl_xor_sync(0xffffffffu, lp0[rg], 2);
        lp1[rg] += __shfl_xor_sync(0xffffffffu, lp1[rg], 1);
        lp1[rg] += __shfl_xor_sync(0xffffffffu, lp1[rg], 2);
        const float il0 = 1.f / lp0[rg];
        const float il1 = 1.f / lp1[rg];
        __half* o0 = ctx + (size_t)(b * SEQ + q0 + wrow + rg * 16 + g) * 1024 + h * 64;
        __half* o1 = o0 + 8 * 1024;
#pragma unroll
        for (int nt = 0; nt < 8; ++nt) {
            *(__half2*)(o0 + nt * 8 + 2 * c) =
                __floats2half2_rn(oacc[rg][nt].x * il0, oacc[rg][nt].y * il0);
            *(__half2*)(o1 + nt * 8 + 2 * c) =
                __floats2half2_rn(oacc[rg][nt].z * il1, oacc[rg][nt].w * il1);
        }
    }
}

// ---------------------------------------------------------------------------
extern "C" void kernel_launch(void* const* d_in, const int* in_sizes, int n_in,
                              void* d_out, int out_size)
{
    const float* x      = (const float*)d_in[0];   // [2,2048,1024]
    const float* w_qkv  = (const float*)d_in[1];   // [1024,3072]
    const float* w_proj = (const float*)d_in[2];   // [1024,1024]
    float* out = (float*)d_out;                    // [2,2048,1024]

    __half *qkv, *ctx, *xh, *wqkvh, *wprojh;
    cudaGetSymbolAddress((void**)&qkv,    g_qkv);
    cudaGetSymbolAddress((void**)&ctx,    g_ctx);
    cudaGetSymbolAddress((void**)&xh,     g_xh);
    cudaGetSymbolAddress((void**)&wqkvh,  g_wqkvh);
    cudaGetSymbolAddress((void**)&wprojh, g_wprojh);

    cudaFuncSetAttribute(gemm_h<true>,  cudaFuncAttributeMaxDynamicSharedMemorySize, GEMM_SMEM);
    cudaFuncSetAttribute(gemm_h<false>, cudaFuncAttributeMaxDynamicSharedMemorySize, GEMM_SMEM);
    cudaFuncSetAttribute(fa_h, cudaFuncAttributeMaxDynamicSharedMemorySize, FA_SMEM);

    // prep: fp32 -> fp16 (single launch)
    f2h3<<<(N4_X + N4_WQ + N4_WP) / 256, 256>>>(
        (const float4*)x, (const float4*)w_qkv, (const float4*)w_proj,
        (__half2*)xh, (__half2*)wqkvh, (__half2*)wprojh);

    const float QSC = 0.125f * 1.44269504088896f;   // (1/sqrt(64)) * log2(e)

    // 1) QKV GEMM: [4096,1024] @ [1024,3072] -> fp16 qkv (q columns pre-scaled)
    gemm_h<true><<<dim3(3 * D_MODEL / 128, M_ROWS / 128), 256, GEMM_SMEM>>>(
        xh, wqkvh, qkv, 3 * D_MODEL, D_MODEL, QSC);

    // 2) Causal flash attention -> fp16 ctx (128 threads, 4 warps x 32 rows)
    fa_h<<<dim3(SEQ / 128, BATCH * N_HEADS), 128, FA_SMEM>>>(qkv, ctx);

    // 3) Projection GEMM: [4096,1024] @ [1024,1024] -> fp32 out
    gemm_h<false><<<dim3(D_MODEL / 128, M_ROWS / 128), 256, GEMM_SMEM>>>(
        ctx, wprojh, out, D_MODEL, 0, 1.0f);
}

// round 14
// speedup vs baseline: 1.0965x; 1.0965x over previous
#include <cuda_runtime.h>
#include <cuda_fp16.h>
#include <cstdint>
#include <cstddef>

#define D_MODEL 1024
#define N_HEADS 16
#define D_HEAD 64
#define BATCH 2
#define SEQ 2048
#define M_ROWS (BATCH * SEQ)   // 4096

// Scratch (allocation-free rule: device globals)
__device__ __half g_qkv[(size_t)M_ROWS * 3 * D_MODEL];     // [4096,3072] fp16
__device__ __half g_ctx[(size_t)M_ROWS * D_MODEL];         // [4096,1024] fp16
__device__ __half g_xh[(size_t)M_ROWS * D_MODEL];          // fp16(x)
__device__ __half g_wqkvh[(size_t)D_MODEL * 3 * D_MODEL];  // fp16(w_qkv) [K,N]
__device__ __half g_wprojh[(size_t)D_MODEL * D_MODEL];     // fp16(w_proj) [K,N]

// ---------------------------------------------------------------------------
// helpers
// ---------------------------------------------------------------------------
__device__ __forceinline__ float ex2(float x) {
    float r;
    asm("ex2.approx.ftz.f32 %0, %1;" : "=f"(r) : "f"(x));
    return r;
}
__device__ __forceinline__ void cpa16(uint32_t dst, const void* src) {
    asm volatile("cp.async.cg.shared.global [%0], [%1], 16;\n" :: "r"(dst), "l"(src));
}
__device__ __forceinline__ uint32_t sm_u32(const void* p) {
    return (uint32_t)__cvta_generic_to_shared(p);
}
__device__ __forceinline__ void ldsm4(uint32_t& r0, uint32_t& r1, uint32_t& r2, uint32_t& r3,
                                      uint32_t addr) {
    asm volatile("ldmatrix.sync.aligned.m8n8.x4.shared.b16 {%0,%1,%2,%3}, [%4];"
                 : "=r"(r0), "=r"(r1), "=r"(r2), "=r"(r3) : "r"(addr));
}
__device__ __forceinline__ void ldsm4t(uint32_t& r0, uint32_t& r1, uint32_t& r2, uint32_t& r3,
                                       uint32_t addr) {
    asm volatile("ldmatrix.sync.aligned.m8n8.x4.trans.shared.b16 {%0,%1,%2,%3}, [%4];"
                 : "=r"(r0), "=r"(r1), "=r"(r2), "=r"(r3) : "r"(addr));
}
// D += A @ B  (m16n8k16, fp16 in, fp32 accumulate)
__device__ __forceinline__ void mma16(float4& d, const uint32_t* a, const uint32_t* b) {
    asm volatile(
        "mma.sync.aligned.m16n8k16.row.col.f32.f16.f16.f32 "
        "{%0,%1,%2,%3},{%4,%5,%6,%7},{%8,%9},{%0,%1,%2,%3};"
        : "+f"(d.x), "+f"(d.y), "+f"(d.z), "+f"(d.w)
        : "r"(a[0]), "r"(a[1]), "r"(a[2]), "r"(a[3]),
          "r"(b[0]), "r"(b[1]));
}
__device__ __forceinline__ uint32_t pack_h2(float a, float b) {
    __half2 h = __floats2half2_rn(a, b);
    return *(uint32_t*)&h;
}

// ---------------------------------------------------------------------------
// prep: fp32 -> fp16 for x, w_qkv, w_proj in ONE launch (float4 granularity)
// ---------------------------------------------------------------------------
#define N4_X  (M_ROWS * D_MODEL / 4)            // 1048576
#define N4_WQ (D_MODEL * 3 * D_MODEL / 4)       // 786432
#define N4_WP (D_MODEL * D_MODEL / 4)           // 262144

__global__ void f2h3(const float4* __restrict__ x, const float4* __restrict__ wq,
                     const float4* __restrict__ wp,
                     __half2* __restrict__ xo, __half2* __restrict__ wqo,
                     __half2* __restrict__ wpo)
{
    const int i = blockIdx.x * blockDim.x + threadIdx.x;
    const float4* in;
    __half2* out;
    int j;
    if (i < N4_X)                { in = x;  out = xo;  j = i; }
    else if (i < N4_X + N4_WQ)   { in = wq; out = wqo; j = i - N4_X; }
    else                         { in = wp; out = wpo; j = i - N4_X - N4_WQ; }
    float4 v = in[j];
    out[j * 2]     = __floats2half2_rn(v.x, v.y);
    out[j * 2 + 1] = __floats2half2_rn(v.z, v.w);
}

// ---------------------------------------------------------------------------
// GEMM: C[M,N] = A[M,1024] @ B[1024,N], fp16 in, fp32 accum, fp16/fp32 out.
// 128x128x32 block tile, FOUR warps (2x2), warp tile 64x64, 4-stage cp.async,
// 2 CTAs/SM (8 warps/SM — barrier stalls in one CTA covered by the other).
// 33% less smem traffic per MAC than the 64x32 config; per-SM smem traffic
// ~100KB/chunk (781 cyc) < HMMA 1024 cyc -> tensor-bound.
// A smem: [128 rows][stride 40 fp16] (80B rows, conflict-free)
// B smem: [32 k][128 n fp16], 16B chunk swizz cc^(k&7) (conflict-free)
// ---------------------------------------------------------------------------
#define GSTAGES 4
#define A_STB (128 * 80)    // 10240 B / stage
#define B_STB (32 * 256)    // 8192 B / stage
#define GEMM_SMEM (GSTAGES * (A_STB + B_STB))   // 73728 B

template<bool HALF_OUT>
__global__ __launch_bounds__(128, 2)
void gemm_h(const __half* __restrict__ A, const __half* __restrict__ B,
            void* __restrict__ Cv, int N, int qcols, float qscale)
{
    extern __shared__ char smc[];
    const uint32_t Ab = sm_u32(smc);
    const uint32_t Bb = Ab + GSTAGES * A_STB;

    const int tid  = threadIdx.x;          // 0..127
    const int lane = tid & 31;
    const int warp = tid >> 5;             // 0..3
    const int g    = lane >> 2;
    const int c    = lane & 3;
    const int l15  = lane & 15;
    const int l16  = lane >> 4;
    const int wm   = (warp & 1) * 64;
    const int wn   = (warp >> 1) * 64;
    const int m0   = blockIdx.y * 128;
    const int n0   = blockIdx.x * 128;

    auto stage = [&](int ch) {
        const int s  = ch & 3;
        const int k0 = ch * 32;
#pragma unroll
        for (int i = 0; i < 4; ++i) {              // A: 128 rows x 4 chunks
            const int id = tid + 128 * i;
            const int row = id >> 2, cc = id & 3;
            cpa16(Ab + s * A_STB + row * 80 + cc * 16,
                  A + (size_t)(m0 + row) * 1024 + k0 + cc * 8);
        }
#pragma unroll
        for (int i = 0; i < 4; ++i) {              // B: 32 k x 16 chunks
            const int id = tid + 128 * i;
            const int row = id >> 4, cc = id & 15;
            cpa16(Bb + s * B_STB + row * 256 + ((cc ^ (row & 7)) * 16),
                  B + (size_t)(k0 + row) * N + n0 + cc * 8);
        }
    };

    stage(0); asm volatile("cp.async.commit_group;\n");
    stage(1); asm volatile("cp.async.commit_group;\n");
    stage(2); asm volatile("cp.async.commit_group;\n");

    float4 acc[4][8];
#pragma unroll
    for (int i = 0; i < 4; ++i)
#pragma unroll
        for (int j = 0; j < 8; ++j) acc[i][j] = make_float4(0.f, 0.f, 0.f, 0.f);

    for (int ch = 0; ch < 32; ++ch) {
        asm volatile("cp.async.wait_group %0;\n" :: "n"(2));
        __syncthreads();

        if (ch + 3 < 32) stage(ch + 3);
        asm volatile("cp.async.commit_group;\n");

        const uint32_t As = Ab + (ch & 3) * A_STB;
        const uint32_t Bs = Bb + (ch & 3) * B_STB;

#pragma unroll
        for (int kc = 0; kc < 2; ++kc) {
            uint32_t af[4][4];
#pragma unroll
            for (int i = 0; i < 4; ++i)
                ldsm4(af[i][0], af[i][1], af[i][2], af[i][3],
                      As + (wm + i * 16 + l15) * 80 + (kc * 2 + l16) * 16);
            uint32_t bf[8][2];
#pragma unroll
            for (int j2 = 0; j2 < 4; ++j2) {
                const int krow = kc * 16 + l15;
                const int cn   = (wn >> 3) + j2 * 2 + l16;
                ldsm4t(bf[j2 * 2][0], bf[j2 * 2][1], bf[j2 * 2 + 1][0], bf[j2 * 2 + 1][1],
                       Bs + krow * 256 + ((cn ^ (krow & 7)) * 16));
            }
#pragma unroll
            for (int i = 0; i < 4; ++i)
#pragma unroll
                for (int j = 0; j < 8; ++j)
                    mma16(acc[i][j], af[i], bf[j]);
        }
    }

    // epilogue (q-column scaling is uniform per CTA: 1024 % 128 == 0)
    const float sc = (n0 < qcols) ? qscale : 1.0f;
#pragma unroll
    for (int i = 0; i < 4; ++i) {
        const int r = m0 + wm + i * 16 + g;
#pragma unroll
        for (int j = 0; j < 8; ++j) {
            const int cl = n0 + wn + j * 8 + 2 * c;
            if (HALF_OUT) {
                __half* C = (__half*)Cv;
                *(__half2*)&C[(size_t)r * N + cl] =
                    __floats2half2_rn(acc[i][j].x * sc, acc[i][j].y * sc);
                *(__half2*)&C[(size_t)(r + 8) * N + cl] =
                    __floats2half2_rn(acc[i][j].z * sc, acc[i][j].w * sc);
            } else {
                float* C = (float*)Cv;
                *(float2*)&C[(size_t)r * N + cl] = make_float2(acc[i][j].x, acc[i][j].y);
                *(float2*)&C[(size_t)(r + 8) * N + cl] = make_float2(acc[i][j].z, acc[i][j].w);
            }
        }
    }
}

// ---------------------------------------------------------------------------
// Flash attention (R12 version — best measured). Causal, fp16 mma + ldmatrix,
// Br=128 (8 warps x 16 q-rows), 128-key super-tile staging (one barrier per
// 128 keys), P in registers, deferred per-thread l, conditional rescale.
// ---------------------------------------------------------------------------
#define KV128_B (128 * 144)                    // 18432 B per K / V 128-row tile
#define FA_SMEM (4 * KV128_B)                  // 73728 B (2 K + 2 V)

__global__ __launch_bounds__(256, 2)
void fa_h(const __half* __restrict__ qkv, __half* __restrict__ ctx)
{
    extern __shared__ char fsc[];
    const uint32_t Kb0 = sm_u32(fsc);              // K buf 0, K buf 1
    const uint32_t Vb0 = Kb0 + 2 * KV128_B;        // V buf 0, V buf 1

    const int tid  = threadIdx.x;
    const int lane = tid & 31;
    const int warp = tid >> 5;
    const int g    = lane >> 2;
    const int c    = lane & 3;
    const int l15  = lane & 15;
    const int l16  = lane >> 4;
    const int bh   = blockIdx.y;
    const int b    = bh >> 4;
    const int h    = bh & 15;
    const int q0   = (gridDim.x - 1 - blockIdx.x) * 128;   // big blocks first
    const int wrow = warp * 16;

    const __half* qbase = qkv + (size_t)(b * SEQ) * 3072 + h * 64;

    // staging: 128 rows x 8 chunks per array = 1024 slots over 256 threads
    const int srow = tid >> 3;            // 0..31
    const int scc  = tid & 7;
    auto stage_kv = [&](int J, int s) {   // stage keys [J, J+128)
        const uint32_t kd = Kb0 + s * KV128_B;
        const uint32_t vd = Vb0 + s * KV128_B;
#pragma unroll
        for (int i = 0; i < 4; ++i) {
            const int row = srow + 32 * i;
            const __half* kg = qbase + (size_t)(J + row) * 3072 + 1024 + scc * 8;
            cpa16(kd + row * 144 + scc * 16, kg);
            cpa16(vd + row * 144 + scc * 16, kg + 1024);
        }
    };

    // Q fragments (already scaled by 0.125*log2e in the QKV GEMM epilogue)
    uint32_t qf[4][4];
    {
        const __half* r0 = qbase + (size_t)(q0 + wrow + g) * 3072;
        const __half* r1 = r0 + 8 * 3072;
#pragma unroll
        for (int kc = 0; kc < 4; ++kc) {
            qf[kc][0] = *(const uint32_t*)(r0 + kc * 16 + 2 * c);
            qf[kc][1] = *(const uint32_t*)(r1 + kc * 16 + 2 * c);
            qf[kc][2] = *(const uint32_t*)(r0 + kc * 16 + 8 + 2 * c);
            qf[kc][3] = *(const uint32_t*)(r1 + kc * 16 + 8 + 2 * c);
        }
    }

    float4 oacc[8];
#pragma unroll
    for (int i = 0; i < 8; ++i) oacc[i] = make_float4(0.f, 0.f, 0.f, 0.f);
    float m0 = -1e30f, m1 = -1e30f;
    float lp0 = 0.f, lp1 = 0.f;       // per-thread partial row sums

    // prologue: stage super-tile 0 into buffer 0
    stage_kv(0, 0);
    asm volatile("cp.async.commit_group;\n");

    int s = 0;
    for (int J = 0; J <= q0; J += 128, s ^= 1) {
        asm volatile("cp.async.wait_group 0;\n");   // super-tile J ready
        __syncthreads();   // publishes J AND proves buffer s^1 is free

        if (J + 128 <= q0) {
            stage_kv(J + 128, s ^ 1);
            asm volatile("cp.async.commit_group;\n");
        }

        // two 64-key halves, computed back-to-back on the same buffer
#pragma unroll
        for (int half = 0; half < 2; ++half) {
            const int j0 = J + half * 64;
            if (j0 > q0 + wrow + 15) break;   // warp fully masked for this half

            const uint32_t Kb = Kb0 + s * KV128_B + half * (64 * 144);
            const uint32_t Vb = Vb0 + s * KV128_B + half * (64 * 144);

            // ---- S = Q @ K^T  (already in log2 domain) ----
            float4 sacc[8];
#pragma unroll
            for (int i = 0; i < 8; ++i) sacc[i] = make_float4(0.f, 0.f, 0.f, 0.f);
#pragma unroll
            for (int kc = 0; kc < 4; ++kc) {
#pragma unroll
                for (int grp = 0; grp < 4; ++grp) {
                    uint32_t r0, r1, r2, r3;
                    ldsm4(r0, r1, r2, r3,
                          Kb + (grp * 16 + l15) * 144 + (kc * 2 + l16) * 16);
                    uint32_t b0[2] = { r0, r2 };
                    uint32_t b1[2] = { r1, r3 };
                    mma16(sacc[2 * grp],     qf[kc], b0);
                    mma16(sacc[2 * grp + 1], qf[kc], b1);
                }
            }

            // ---- causal mask (only near the diagonal) ----
            if (j0 + 63 > q0 + wrow) {
                const int rg = q0 + wrow + g;
#pragma unroll
                for (int nt = 0; nt < 8; ++nt) {
                    const int cl = j0 + nt * 8 + 2 * c;
                    if (cl     > rg)     sacc[nt].x = -1e30f;
                    if (cl + 1 > rg)     sacc[nt].y = -1e30f;
                    if (cl     > rg + 8) sacc[nt].z = -1e30f;
                    if (cl + 1 > rg + 8) sacc[nt].w = -1e30f;
                }
            }

            // ---- online softmax (deferred l; conditional rescale) ----
            float tm0 = -1e30f, tm1 = -1e30f;
#pragma unroll
            for (int nt = 0; nt < 8; ++nt) {
                tm0 = fmaxf(tm0, fmaxf(sacc[nt].x, sacc[nt].y));
                tm1 = fmaxf(tm1, fmaxf(sacc[nt].z, sacc[nt].w));
            }
            tm0 = fmaxf(tm0, __shfl_xor_sync(0xffffffffu, tm0, 1));
            tm0 = fmaxf(tm0, __shfl_xor_sync(0xffffffffu, tm0, 2));
            tm1 = fmaxf(tm1, __shfl_xor_sync(0xffffffffu, tm1, 1));
            tm1 = fmaxf(tm1, __shfl_xor_sync(0xffffffffu, tm1, 2));

            if (tm0 > m0 || tm1 > m1) {            // max moved: rescale state
                const float nm0 = fmaxf(m0, tm0);
                const float nm1 = fmaxf(m1, tm1);
                const float cr0 = ex2(m0 - nm0);
                const float cr1 = ex2(m1 - nm1);
                m0 = nm0; m1 = nm1;
                lp0 *= cr0; lp1 *= cr1;
#pragma unroll
                for (int nt = 0; nt < 8; ++nt) {
                    oacc[nt].x *= cr0; oacc[nt].y *= cr0;
                    oacc[nt].z *= cr1; oacc[nt].w *= cr1;
                }
            }

            float ps0 = 0.f, ps1 = 0.f;
#pragma unroll
            for (int nt = 0; nt < 8; ++nt) {
                sacc[nt].x = ex2(sacc[nt].x - m0);
                sacc[nt].y = ex2(sacc[nt].y - m0);
                sacc[nt].z = ex2(sacc[nt].z - m1);
                sacc[nt].w = ex2(sacc[nt].w - m1);
                ps0 += sacc[nt].x + sacc[nt].y;
                ps1 += sacc[nt].z + sacc[nt].w;
            }
            lp0 += ps0;        // per-thread partial; reduced once at the end
            lp1 += ps1;

            // ---- pack P into A-operand fragments (registers only) ----
            uint32_t pf[16];
#pragma unroll
            for (int nt = 0; nt < 8; ++nt) {
                pf[nt * 2]     = pack_h2(sacc[nt].x, sacc[nt].y);
                pf[nt * 2 + 1] = pack_h2(sacc[nt].z, sacc[nt].w);
            }

            // ---- O += P @ V ----
#pragma unroll
            for (int kc = 0; kc < 4; ++kc) {
                const uint32_t* af = &pf[kc * 4];
#pragma unroll
                for (int j2 = 0; j2 < 4; ++j2) {
                    uint32_t r0, r1, r2, r3;
                    ldsm4t(r0, r1, r2, r3,
                           Vb + (kc * 16 + l15) * 144 + (j2 * 2 + l16) * 16);
                    uint32_t b0[2] = { r0, r1 };
                    uint32_t b1[2] = { r2, r3 };
                    mma16(oacc[2 * j2],     af, b0);
                    mma16(oacc[2 * j2 + 1], af, b1);
                }
            }
        }
    }

    // ---- final l reduction (once) + normalize + write ctx (fp16) ----
    lp0 += __shfl_xor_sync(0xffffffffu, lp0, 1);
    lp0 += __shfl_xor_sync(0xffffffffu, lp0, 2);
    lp1 += __shfl_xor_sync(0xffffffffu, lp1, 1);
    lp1 += __shfl_xor_sync(0xffffffffu, lp1, 2);
    const float il0 = 1.f / lp0;
    const float il1 = 1.f / lp1;
    __half* o0 = ctx + (size_t)(b * SEQ + q0 + wrow + g) * 1024 + h * 64;
    __half* o1 = o0 + 8 * 1024;
#pragma unroll
    for (int nt = 0; nt < 8; ++nt) {
        *(__half2*)(o0 + nt * 8 + 2 * c) =
            __floats2half2_rn(oacc[nt].x * il0, oacc[nt].y * il0);
        *(__half2*)(o1 + nt * 8 + 2 * c) =
            __floats2half2_rn(oacc[nt].z * il1, oacc[nt].w * il1);
    }
}

// ---------------------------------------------------------------------------
extern "C" void kernel_launch(void* const* d_in, const int* in_sizes, int n_in,
                              void* d_out, int out_size)
{
    const float* x      = (const float*)d_in[0];   // [2,2048,1024]
    const float* w_qkv  = (const float*)d_in[1];   // [1024,3072]
    const float* w_proj = (const float*)d_in[2];   // [1024,1024]
    float* out = (float*)d_out;                    // [2,2048,1024]

    __half *qkv, *ctx, *xh, *wqkvh, *wprojh;
    cudaGetSymbolAddress((void**)&qkv,    g_qkv);
    cudaGetSymbolAddress((void**)&ctx,    g_ctx);
    cudaGetSymbolAddress((void**)&xh,     g_xh);
    cudaGetSymbolAddress((void**)&wqkvh,  g_wqkvh);
    cudaGetSymbolAddress((void**)&wprojh, g_wprojh);

    cudaFuncSetAttribute(gemm_h<true>,  cudaFuncAttributeMaxDynamicSharedMemorySize, GEMM_SMEM);
    cudaFuncSetAttribute(gemm_h<false>, cudaFuncAttributeMaxDynamicSharedMemorySize, GEMM_SMEM);
    cudaFuncSetAttribute(fa_h, cudaFuncAttributeMaxDynamicSharedMemorySize, FA_SMEM);

    // prep: fp32 -> fp16 (single launch)
    f2h3<<<(N4_X + N4_WQ + N4_WP) / 256, 256>>>(
        (const float4*)x, (const float4*)w_qkv, (const float4*)w_proj,
        (__half2*)xh, (__half2*)wqkvh, (__half2*)wprojh);

    const float QSC = 0.125f * 1.44269504088896f;   // (1/sqrt(64)) * log2(e)

    // 1) QKV GEMM: [4096,1024] @ [1024,3072] -> fp16 qkv (q columns pre-scaled)
    gemm_h<true><<<dim3(3 * D_MODEL / 128, M_ROWS / 128), 128, GEMM_SMEM>>>(
        xh, wqkvh, qkv, 3 * D_MODEL, D_MODEL, QSC);

    // 2) Causal flash attention -> fp16 ctx
    fa_h<<<dim3(SEQ / 128, BATCH * N_HEADS), 256, FA_SMEM>>>(qkv, ctx);

    // 3) Projection GEMM: [4096,1024] @ [1024,1024] -> fp32 out
    gemm_h<false><<<dim3(D_MODEL / 128, M_ROWS / 128), 128, GEMM_SMEM>>>(
        ctx, wprojh, out, D_MODEL, 0, 1.0f);
}